// round 16
// baseline (speedup 1.0000x reference)
#include <cuda_runtime.h>
#include <cuda_fp16.h>
#include <cstdint>

#define BATCH 4
#define C_DIM 128
#define HW_BIG 65536
#define HW_SM 16384
#define W_BIG 256
#define K_NBR 16
#define TRANS_BLKS (HW_BIG / 32)   // 2048 tiles per array

// Per-batch scratches. Keys fp32 (33.5MB) + values fp16 (16.8MB) = 50MB,
// L2-resident, reused at the same addresses every batch.
__device__ float  g_TS[(size_t)HW_BIG * C_DIM];
__device__ __half g_TR[(size_t)HW_BIG * C_DIM];

// ---------------------------------------------------------------------------
// Combined transpose (one launch per batch, both arrays): latency-bound
// streams stack and saturate the chip LTS cap.
//   blocks [0, 2048)    : S tile -> g_TS (fp32)
//   blocks [2048, 4096) : R tile -> g_TR (fp16)
// ---------------------------------------------------------------------------
__global__ __launch_bounds__(256)
void k_trans2(const float* __restrict__ S, const float* __restrict__ R)
{
    __shared__ float tile[32][129];
    const bool isR = blockIdx.x >= TRANS_BLKS;
    const int  blk = isR ? (blockIdx.x - TRANS_BLKS) : blockIdx.x;
    const float* in = isR ? R : S;

    const int p0 = blk * 32;
    const int t  = threadIdx.x;

    #pragma unroll
    for (int i0 = 0; i0 < 4; i0++) {
        const int g  = t + 256 * i0;
        const int c  = g >> 3;
        const int pq = (g & 7) * 4;
        const float4 v = __ldcs(reinterpret_cast<const float4*>(
            in + (size_t)c * HW_BIG + p0 + pq));
        tile[pq + 0][c] = v.x;
        tile[pq + 1][c] = v.y;
        tile[pq + 2][c] = v.z;
        tile[pq + 3][c] = v.w;
    }
    __syncthreads();

    const int p = t >> 3;
    if (!isR) {
        #pragma unroll
        for (int i0 = 0; i0 < 4; i0++) {
            const int cg = (t & 7) + 8 * i0;
            const float4 v = make_float4(tile[p][4*cg + 0], tile[p][4*cg + 1],
                                         tile[p][4*cg + 2], tile[p][4*cg + 3]);
            *reinterpret_cast<float4*>(g_TS + (size_t)(p0 + p) * C_DIM + 4*cg) = v;
        }
    } else {
        #pragma unroll
        for (int i0 = 0; i0 < 4; i0++) {
            const int cg = (t & 7) + 8 * i0;
            const __half2 h0 = __floats2half2_rn(tile[p][4*cg + 0], tile[p][4*cg + 1]);
            const __half2 h1 = __floats2half2_rn(tile[p][4*cg + 2], tile[p][4*cg + 3]);
            uint2 u;
            u.x = *reinterpret_cast<const unsigned int*>(&h0);
            u.y = *reinterpret_cast<const unsigned int*>(&h1);
            *reinterpret_cast<uint2*>(g_TR + (size_t)(p0 + p) * C_DIM + 4*cg) = u;
        }
    }
}

// ---------------------------------------------------------------------------
// Score pass: warp-per-pixel, fp32 key gathers in groups of 8, softmax,
// writes normalized weights. Per-group index computation keeps live regs
// within the (256,4) bound -> occ >= 50%.
// ---------------------------------------------------------------------------
__global__ __launch_bounds__(256, 4)
void k_score(const float* __restrict__ Q,     // batch: C x HW_SM
             const int*   __restrict__ PosY,
             const int*   __restrict__ PosX,
             float*       __restrict__ outM)  // batch: HW_SM * K
{
    __shared__ float Qs[8][132];
    const int t  = threadIdx.x;
    const int p0 = blockIdx.x * 8;

    #pragma unroll
    for (int i = 0; i < 4; i++) {
        const int c  = (t >> 3) + 32 * i;
        const int px = t & 7;
        Qs[px][c] = __ldcs(Q + (size_t)c * HW_SM + p0 + px);
    }
    __syncthreads();

    const int warpId = t >> 5, lane = t & 31;
    const int p = p0 + warpId;
    const float4 q4 = reinterpret_cast<const float4*>(&Qs[warpId][0])[lane];

    const int4* py4 = reinterpret_cast<const int4*>(PosY + (size_t)p * K_NBR);
    const int4* px4 = reinterpret_cast<const int4*>(PosX + (size_t)p * K_NBR);

    float sc[K_NBR];
    #pragma unroll
    for (int g = 0; g < 2; g++) {
        // indices for this group only (short-lived regs)
        const int4 y0 = py4[2*g + 0], y1 = py4[2*g + 1];
        const int4 x0 = px4[2*g + 0], x1 = px4[2*g + 1];
        int idx[8];
        idx[0] = y0.x * W_BIG + x0.x;  idx[1] = y0.y * W_BIG + x0.y;
        idx[2] = y0.z * W_BIG + x0.z;  idx[3] = y0.w * W_BIG + x0.w;
        idx[4] = y1.x * W_BIG + x1.x;  idx[5] = y1.y * W_BIG + x1.y;
        idx[6] = y1.z * W_BIG + x1.z;  idx[7] = y1.w * W_BIG + x1.w;

        float4 kv[8];
        #pragma unroll
        for (int j = 0; j < 8; j++)
            kv[j] = reinterpret_cast<const float4*>(
                g_TS + (size_t)idx[j] * C_DIM)[lane];
        #pragma unroll
        for (int j = 0; j < 8; j++)
            sc[g*8 + j] = q4.x*kv[j].x + q4.y*kv[j].y
                        + q4.z*kv[j].z + q4.w*kv[j].w;
    }

    #pragma unroll
    for (int st = 16; st >= 1; st >>= 1) {
        #pragma unroll
        for (int j = 0; j < K_NBR; j++)
            sc[j] += __shfl_xor_sync(0xffffffffu, sc[j], st);
    }

    float m = sc[0];
    #pragma unroll
    for (int j = 1; j < K_NBR; j++) m = fmaxf(m, sc[j]);
    float s = 0.f;
    #pragma unroll
    for (int j = 0; j < K_NBR; j++) { sc[j] = __expf(sc[j] - m); s += sc[j]; }
    const float inv = 1.0f / s;

    if (lane < K_NBR)
        __stcs(outM + (size_t)p * K_NBR + lane, sc[lane] * inv);
}

// ---------------------------------------------------------------------------
// Value pass: warp-per-pixel, fp16 value gathers in groups of 8, weighted sum
// with weights from M (uniform float4 loads), coalesced channel-major output.
// ---------------------------------------------------------------------------
__global__ __launch_bounds__(256)
void k_value(const int*   __restrict__ PosY,
             const int*   __restrict__ PosX,
             const float* __restrict__ M,      // batch: HW_SM * K
             float*       __restrict__ outBuf) // batch: C x HW_SM
{
    const int t = threadIdx.x, warpId = t >> 5, lane = t & 31;
    const int p0 = blockIdx.x * 8;
    const int p  = p0 + warpId;

    const int4*   py4 = reinterpret_cast<const int4*>(PosY + (size_t)p * K_NBR);
    const int4*   px4 = reinterpret_cast<const int4*>(PosX + (size_t)p * K_NBR);
    const float4* m4  = reinterpret_cast<const float4*>(M + (size_t)p * K_NBR);

    float4 acc = make_float4(0.f, 0.f, 0.f, 0.f);
    #pragma unroll
    for (int g = 0; g < 2; g++) {
        const int4 y0 = py4[2*g + 0], y1 = py4[2*g + 1];
        const int4 x0 = px4[2*g + 0], x1 = px4[2*g + 1];
        const float4 w0 = m4[2*g + 0], w1 = m4[2*g + 1];
        int   idx[8];
        float w[8];
        idx[0] = y0.x * W_BIG + x0.x;  w[0] = w0.x;
        idx[1] = y0.y * W_BIG + x0.y;  w[1] = w0.y;
        idx[2] = y0.z * W_BIG + x0.z;  w[2] = w0.z;
        idx[3] = y0.w * W_BIG + x0.w;  w[3] = w0.w;
        idx[4] = y1.x * W_BIG + x1.x;  w[4] = w1.x;
        idx[5] = y1.y * W_BIG + x1.y;  w[5] = w1.y;
        idx[6] = y1.z * W_BIG + x1.z;  w[6] = w1.z;
        idx[7] = y1.w * W_BIG + x1.w;  w[7] = w1.w;

        uint2 kv[8];
        #pragma unroll
        for (int j = 0; j < 8; j++)
            kv[j] = reinterpret_cast<const uint2*>(
                g_TR + (size_t)idx[j] * C_DIM)[lane];
        #pragma unroll
        for (int j = 0; j < 8; j++) {
            const __half2 h0 = *reinterpret_cast<const __half2*>(&kv[j].x);
            const __half2 h1 = *reinterpret_cast<const __half2*>(&kv[j].y);
            const float2 f0 = __half22float2(h0);
            const float2 f1 = __half22float2(h1);
            acc.x += w[j] * f0.x;
            acc.y += w[j] * f0.y;
            acc.z += w[j] * f1.x;
            acc.w += w[j] * f1.y;
        }
    }

    __shared__ float so[8][132];
    reinterpret_cast<float4*>(&so[warpId][0])[lane] = acc;
    __syncthreads();

    const int px = t & 7;
    const int c0 = t >> 3;
    #pragma unroll
    for (int r = 0; r < 4; r++) {
        const int c = c0 + 32 * r;
        __stcs(outBuf + (size_t)c * HW_SM + p0 + px, so[px][c]);
    }
}

extern "C" void kernel_launch(void* const* d_in, const int* in_sizes, int n_in,
                              void* d_out, int out_size)
{
    const float* Q   = (const float*)d_in[0];
    const float* S   = (const float*)d_in[1];
    const float* R   = (const float*)d_in[2];
    const int*   Pos = (const int*)d_in[3];

    float* outBuf = (float*)d_out;                                // B*C*hw
    float* outM   = outBuf + (size_t)BATCH * C_DIM * HW_SM;       // B*hw*k

    for (int b = 0; b < BATCH; b++) {
        const float* Sb = S + (size_t)b * C_DIM * HW_BIG;
        const float* Rb = R + (size_t)b * C_DIM * HW_BIG;
        const float* Qb = Q + (size_t)b * C_DIM * HW_SM;
        const int*   PY = Pos + (size_t)b * 2 * HW_SM * K_NBR;
        const int*   PX = PY + (size_t)HW_SM * K_NBR;
        float*       Mb = outM   + (size_t)b * HW_SM * K_NBR;
        float*       Ob = outBuf + (size_t)b * C_DIM * HW_SM;

        k_trans2<<<2 * TRANS_BLKS, 256>>>(Sb, Rb);
        k_score <<<HW_SM / 8, 256>>>(Qb, PY, PX, Mb);
        k_value <<<HW_SM / 8, 256>>>(PY, PX, Mb, Ob);
    }
}

// round 17
// speedup vs baseline: 1.0475x; 1.0475x over previous
#include <cuda_runtime.h>
#include <cuda_fp16.h>
#include <cstdint>

#define BATCH 4
#define C_DIM 128
#define HW_BIG 65536
#define HW_SM 16384
#define W_BIG 256
#define K_NBR 16
#define TRANS_BLKS (HW_BIG / 32)   // 2048 tiles per array

// Per-batch scratches. Keys fp32 (33.5MB) + values fp16 (16.8MB) = 50MB,
// L2-resident, reused at the same addresses every batch.
__device__ float  g_TS[(size_t)HW_BIG * C_DIM];
__device__ __half g_TR[(size_t)HW_BIG * C_DIM];

// ---------------------------------------------------------------------------
// Combined transpose (one launch per batch, both arrays): the two
// latency-bound streams stack and saturate the chip LTS cap.
//   blocks [0, 2048)    : S tile -> g_TS (fp32)
//   blocks [2048, 4096) : R tile -> g_TR (fp16)
// ---------------------------------------------------------------------------
__global__ __launch_bounds__(256)
void k_trans2(const float* __restrict__ S, const float* __restrict__ R)
{
    __shared__ float tile[32][129];
    const bool isR = blockIdx.x >= TRANS_BLKS;
    const int  blk = isR ? (blockIdx.x - TRANS_BLKS) : blockIdx.x;
    const float* in = isR ? R : S;

    const int p0 = blk * 32;
    const int t  = threadIdx.x;

    #pragma unroll
    for (int i0 = 0; i0 < 4; i0++) {
        const int g  = t + 256 * i0;
        const int c  = g >> 3;
        const int pq = (g & 7) * 4;
        const float4 v = __ldcs(reinterpret_cast<const float4*>(
            in + (size_t)c * HW_BIG + p0 + pq));
        tile[pq + 0][c] = v.x;
        tile[pq + 1][c] = v.y;
        tile[pq + 2][c] = v.z;
        tile[pq + 3][c] = v.w;
    }
    __syncthreads();

    const int p = t >> 3;
    if (!isR) {
        #pragma unroll
        for (int i0 = 0; i0 < 4; i0++) {
            const int cg = (t & 7) + 8 * i0;
            const float4 v = make_float4(tile[p][4*cg + 0], tile[p][4*cg + 1],
                                         tile[p][4*cg + 2], tile[p][4*cg + 3]);
            *reinterpret_cast<float4*>(g_TS + (size_t)(p0 + p) * C_DIM + 4*cg) = v;
        }
    } else {
        #pragma unroll
        for (int i0 = 0; i0 < 4; i0++) {
            const int cg = (t & 7) + 8 * i0;
            const __half2 h0 = __floats2half2_rn(tile[p][4*cg + 0], tile[p][4*cg + 1]);
            const __half2 h1 = __floats2half2_rn(tile[p][4*cg + 2], tile[p][4*cg + 3]);
            uint2 u;
            u.x = *reinterpret_cast<const unsigned int*>(&h0);
            u.y = *reinterpret_cast<const unsigned int*>(&h1);
            *reinterpret_cast<uint2*>(g_TR + (size_t)(p0 + p) * C_DIM + 4*cg) = u;
        }
    }
}

// ---------------------------------------------------------------------------
// Fused attention, register-disciplined: gathers in groups of 4, indices
// recomputed per group per phase from Pos (uniform, L2-hit). Peak live set
// fits 64 regs -> 4 blocks/SM.
// ---------------------------------------------------------------------------
__global__ __launch_bounds__(256, 4)
void attn_fused_kernel(const float* __restrict__ Q,     // batch: C x HW_SM
                       const int*   __restrict__ PosY,
                       const int*   __restrict__ PosX,
                       float*       __restrict__ outM,  // batch: HW_SM * K
                       float*       __restrict__ outBuf)// batch: C x HW_SM
{
    __shared__ float stage[8][132];
    const int t  = threadIdx.x;
    const int p0 = blockIdx.x * 8;

    #pragma unroll
    for (int i = 0; i < 4; i++) {
        const int c  = (t >> 3) + 32 * i;
        const int px = t & 7;
        stage[px][c] = __ldcs(Q + (size_t)c * HW_SM + p0 + px);
    }
    __syncthreads();

    const int warpId = t >> 5, lane = t & 31;
    const int p = p0 + warpId;

    const float4 q4 = reinterpret_cast<const float4*>(&stage[warpId][0])[lane];
    __syncthreads();   // stage reused for output

    const int4* py4 = reinterpret_cast<const int4*>(PosY + (size_t)p * K_NBR);
    const int4* px4 = reinterpret_cast<const int4*>(PosX + (size_t)p * K_NBR);

    // ---- score gathers (fp32 keys), groups of 4, idx recomputed per group ----
    float sc[K_NBR];
    #pragma unroll
    for (int g = 0; g < 4; g++) {
        const int4 y = py4[g];
        const int4 x = px4[g];
        int idx[4];
        idx[0] = y.x * W_BIG + x.x;
        idx[1] = y.y * W_BIG + x.y;
        idx[2] = y.z * W_BIG + x.z;
        idx[3] = y.w * W_BIG + x.w;

        float4 kv[4];
        #pragma unroll
        for (int j = 0; j < 4; j++)
            kv[j] = reinterpret_cast<const float4*>(
                g_TS + (size_t)idx[j] * C_DIM)[lane];
        #pragma unroll
        for (int j = 0; j < 4; j++)
            sc[g*4 + j] = q4.x*kv[j].x + q4.y*kv[j].y
                        + q4.z*kv[j].z + q4.w*kv[j].w;
    }

    #pragma unroll
    for (int st = 16; st >= 1; st >>= 1) {
        #pragma unroll
        for (int j = 0; j < K_NBR; j++)
            sc[j] += __shfl_xor_sync(0xffffffffu, sc[j], st);
    }

    // ---- softmax ----
    float m = sc[0];
    #pragma unroll
    for (int j = 1; j < K_NBR; j++) m = fmaxf(m, sc[j]);
    float s = 0.f;
    #pragma unroll
    for (int j = 0; j < K_NBR; j++) { sc[j] = __expf(sc[j] - m); s += sc[j]; }
    const float inv = 1.0f / s;
    #pragma unroll
    for (int j = 0; j < K_NBR; j++) sc[j] *= inv;

    if (lane < K_NBR)
        outM[(size_t)p * K_NBR + lane] = sc[lane];

    // ---- value gathers (fp16 values), groups of 4, idx recomputed ----
    float4 acc = make_float4(0.f, 0.f, 0.f, 0.f);
    #pragma unroll
    for (int g = 0; g < 4; g++) {
        const int4 y = py4[g];
        const int4 x = px4[g];
        int idx[4];
        idx[0] = y.x * W_BIG + x.x;
        idx[1] = y.y * W_BIG + x.y;
        idx[2] = y.z * W_BIG + x.z;
        idx[3] = y.w * W_BIG + x.w;

        uint2 kv[4];
        #pragma unroll
        for (int j = 0; j < 4; j++)
            kv[j] = reinterpret_cast<const uint2*>(
                g_TR + (size_t)idx[j] * C_DIM)[lane];
        #pragma unroll
        for (int j = 0; j < 4; j++) {
            const float w = sc[g*4 + j];
            const __half2 h0 = *reinterpret_cast<const __half2*>(&kv[j].x);
            const __half2 h1 = *reinterpret_cast<const __half2*>(&kv[j].y);
            const float2 f0 = __half22float2(h0);
            const float2 f1 = __half22float2(h1);
            acc.x += w * f0.x;
            acc.y += w * f0.y;
            acc.z += w * f1.x;
            acc.w += w * f1.y;
        }
    }

    // ---- coalesced channel-major buffer store via smem ----
    reinterpret_cast<float4*>(&stage[warpId][0])[lane] = acc;
    __syncthreads();

    const int px = t & 7;
    const int c0 = t >> 3;
    #pragma unroll
    for (int r = 0; r < 4; r++) {
        const int c = c0 + 32 * r;
        __stcs(outBuf + (size_t)c * HW_SM + p0 + px, stage[px][c]);
    }
}

extern "C" void kernel_launch(void* const* d_in, const int* in_sizes, int n_in,
                              void* d_out, int out_size)
{
    const float* Q   = (const float*)d_in[0];
    const float* S   = (const float*)d_in[1];
    const float* R   = (const float*)d_in[2];
    const int*   Pos = (const int*)d_in[3];

    float* outBuf = (float*)d_out;                                // B*C*hw
    float* outM   = outBuf + (size_t)BATCH * C_DIM * HW_SM;       // B*hw*k

    for (int b = 0; b < BATCH; b++) {
        const float* Sb = S + (size_t)b * C_DIM * HW_BIG;
        const float* Rb = R + (size_t)b * C_DIM * HW_BIG;
        const float* Qb = Q + (size_t)b * C_DIM * HW_SM;
        const int*   PY = Pos + (size_t)b * 2 * HW_SM * K_NBR;
        const int*   PX = PY + (size_t)HW_SM * K_NBR;
        float*       Mb = outM   + (size_t)b * HW_SM * K_NBR;
        float*       Ob = outBuf + (size_t)b * C_DIM * HW_SM;

        k_trans2<<<2 * TRANS_BLKS, 256>>>(Sb, Rb);
        attn_fused_kernel<<<HW_SM / 8, 256>>>(Qb, PY, PX, Mb, Ob);
    }
}